// round 10
// baseline (speedup 1.0000x reference)
#include <cuda_runtime.h>
#include <cuda_bf16.h>

// Piecewise-linear LUT (65 knots, uniform grid [-8,8], h=0.25).
// Exact searchsorted(side='right') index with NO fixup:
//   idx = floor(4x + 32) = floor(4x) + 32, and 4*x is EXACT in fp32
//   (power-of-two multiply), so __float2int_rd(4x) + 32 is the exact index.
// Per element: FMUL + F2I + 2*IMNMX + conflict-free LDS.64 + FFMA.
// Out-of-range and the reference's "+1 for x >= xs[63]" quirk live in
// sentinel records 0 / 65 and record 64's intercept.
//
// R10 (final): best-measured operating point — TPB=256, VPT=4, __ldcs
// streaming both ways, launch_bounds(256,8), lean table build. Host selects
// an unguarded kernel when n4 divides the per-block tile exactly (true for
// this shape), removing all bounds checks from the hot path.
// Measured plateau: ~6.2 TB/s DRAM (77-79% of spec) across all configs —
// this is the 1R:1W streaming roofline on GB300.

#define NPTS 65
#define NSEG 64
#define NREC 66   // record j covers segment j-1; j=0 below-range, j=65 above
#define VPT  4    // float4s per thread
#define TPB  256

__device__ __forceinline__ float eval_rec(float xv,
                                          const float2* __restrict__ p_lane)
{
    // i = floor(4x), exact (power-of-two multiply). Record = i+33 in [0,65].
    int i = __float2int_rd(xv * 4.0f);
    i = max(-33, min(i, 32));
    float2 ab = p_lane[i * 32];            // lane-private bank pair: conflict-free
    return fmaf(ab.x, xv, ab.y);
}

__device__ __forceinline__ void build_table(const float* __restrict__ table,
                                            float2* s_ab0, float2* s_ab, int t)
{
    if (t < NREC) {
        float a, b;
        if (t == 0)             { a = 0.0f; b = 0.0f; }   // x < xs[0]
        else if (t == NREC - 1) { a = 0.0f; b = 1.0f; }   // x >= xs[64]
        else {
            int k = t - 1;                                 // segment 0..63
            float x0 = table[2 * k + 0],     y0 = table[2 * k + 1];
            float x1 = table[2 * k + 2],     y1 = table[2 * k + 3];
            a = (y1 - y0) / (x1 - x0);
            b = y0 - a * x0;
            if (k == NSEG - 1) b += 1.0f;  // fold "+1 for x >= xs[63]"
        }
        s_ab0[t] = make_float2(a, b);
    }
    __syncthreads();
    for (int i = t; i < NREC * 32; i += blockDim.x)
        s_ab[i] = s_ab0[i >> 5];
    __syncthreads();
}

__device__ __forceinline__ float4 eval4(float4 v, const float2* p_lane)
{
    float4 r;
    r.x = eval_rec(v.x, p_lane);
    r.y = eval_rec(v.y, p_lane);
    r.z = eval_rec(v.z, p_lane);
    r.w = eval_rec(v.w, p_lane);
    return r;
}

// Unguarded fast kernel: host guarantees n4 == gridDim.x * TPB * VPT.
__global__ void __launch_bounds__(TPB, 8)
cSigmoid_pwl_kernel_exact(const float4* __restrict__ x4,
                          const float*  __restrict__ table,
                          float4* __restrict__ out4)
{
    __shared__ float2 s_ab0[NREC];
    __shared__ float2 s_ab[NREC * 32];

    int t = threadIdx.x;
    build_table(table, s_ab0, s_ab, t);

    const float2* p_lane = s_ab + (t & 31) + 33 * 32;

    int base = blockIdx.x * (TPB * VPT) + t;

    float4 v[VPT];
#pragma unroll
    for (int k = 0; k < VPT; k++)
        v[k] = __ldcs(&x4[base + k * TPB]);
#pragma unroll
    for (int k = 0; k < VPT; k++)
        __stcs(&out4[base + k * TPB], eval4(v[k], p_lane));
}

// Guarded variant for general n4.
__global__ void __launch_bounds__(TPB, 8)
cSigmoid_pwl_kernel(const float4* __restrict__ x4,
                    const float*  __restrict__ table,
                    float4* __restrict__ out4,
                    int n4)
{
    __shared__ float2 s_ab0[NREC];
    __shared__ float2 s_ab[NREC * 32];

    int t = threadIdx.x;
    build_table(table, s_ab0, s_ab, t);

    const float2* p_lane = s_ab + (t & 31) + 33 * 32;

    int base = blockIdx.x * (TPB * VPT) + t;

    if (base + (VPT - 1) * TPB < n4) {
        float4 v[VPT];
#pragma unroll
        for (int k = 0; k < VPT; k++)
            v[k] = __ldcs(&x4[base + k * TPB]);
#pragma unroll
        for (int k = 0; k < VPT; k++)
            __stcs(&out4[base + k * TPB], eval4(v[k], p_lane));
    } else {
#pragma unroll
        for (int k = 0; k < VPT; k++) {
            int i = base + k * TPB;
            if (i < n4) __stcs(&out4[i], eval4(__ldcs(&x4[i]), p_lane));
        }
    }
}

// Scalar tail (n % 4 != 0); not hit for this shape but kept for generality.
__global__ void cSigmoid_pwl_tail_kernel(const float* __restrict__ x,
                                         const float* __restrict__ table,
                                         float* __restrict__ out,
                                         int start, int n)
{
    __shared__ float2 s_ab0[NREC];
    __shared__ float2 s_ab[NREC * 32];

    int t = threadIdx.x;
    build_table(table, s_ab0, s_ab, t);

    const float2* p_lane = s_ab + (t & 31) + 33 * 32;

    int i = start + blockIdx.x * blockDim.x + t;
    if (i < n) out[i] = eval_rec(x[i], p_lane);
}

extern "C" void kernel_launch(void* const* d_in, const int* in_sizes, int n_in,
                              void* d_out, int out_size)
{
    const float* x     = (const float*)d_in[0];
    const float* table = (const float*)d_in[1];
    float* out         = (float*)d_out;

    int n  = in_sizes[0];
    int n4 = n / 4;

    if (n4 > 0) {
        const int per_block = TPB * VPT;
        if (n4 % per_block == 0) {
            cSigmoid_pwl_kernel_exact<<<n4 / per_block, TPB>>>(
                (const float4*)x, table, (float4*)out);
        } else {
            int blocks = (n4 + per_block - 1) / per_block;
            cSigmoid_pwl_kernel<<<blocks, TPB>>>(
                (const float4*)x, table, (float4*)out, n4);
        }
    }

    int tail = n - n4 * 4;
    if (tail > 0) {
        cSigmoid_pwl_tail_kernel<<<1, 256>>>(x, table, out, n4 * 4, n);
    }
}